// round 10
// baseline (speedup 1.0000x reference)
#include <cuda_runtime.h>
#include <cuda_bf16.h>
#include <math.h>

// Problem constants
#define N_IMG  32
#define CI_TOT 64
#define HH     128
#define WW     128
#define CO_TOT 128
#define HO     126
#define WO     126

#define TPX 16
#define TPY 16

// ---- packed operand scratch (device globals; no allocation) ----
// g_xP2: bf16x2, [n(32)][chunk(4)][h(128)][w(128)][ci2-in-chunk(8)]  (32B per site)
__device__ unsigned g_xP2[32u * 4u * 128u * 128u * 8u];
// g_wP3: pre-swizzled smem byte image of ws: [chunk(4)][tap(9)][256 units x 16B]
__device__ uint4 g_wP3[4 * 9 * 256];

// pack_x v3: 2 w-positions per thread, float2 loads, 64B contiguous stores
__global__ void pack_x_kernel(const float* __restrict__ x) {
    unsigned i = blockIdx.x * 256 + threadIdx.x;   // 1,048,576 threads
    unsigned w2    = (i & 63) * 2;
    unsigned h     = (i >> 6) & 127;
    unsigned chunk = (i >> 13) & 3;
    unsigned n     = i >> 15;
    const float* src = x + (((size_t)(n * 64 + chunk * 16)) * 128 + h) * 128 + w2;
    unsigned o0[8], o1[8];
#pragma unroll
    for (int c2 = 0; c2 < 8; c2++) {
        float2 f0 = *reinterpret_cast<const float2*>(src + (size_t)(2 * c2) * 16384);
        float2 f1 = *reinterpret_cast<const float2*>(src + (size_t)(2 * c2 + 1) * 16384);
        __nv_bfloat162 p0 = __float22bfloat162_rn(make_float2(f0.x, f1.x));
        __nv_bfloat162 p1 = __float22bfloat162_rn(make_float2(f0.y, f1.y));
        o0[c2] = *reinterpret_cast<unsigned*>(&p0);
        o1[c2] = *reinterpret_cast<unsigned*>(&p1);
    }
    uint4* dst = reinterpret_cast<uint4*>(
        &g_xP2[((((size_t)n * 4 + chunk) * 128 + h) * 128 + w2) * 8]);
    dst[0] = make_uint4(o0[0], o0[1], o0[2], o0[3]);
    dst[1] = make_uint4(o0[4], o0[5], o0[6], o0[7]);
    dst[2] = make_uint4(o1[0], o1[1], o1[2], o1[3]);
    dst[3] = make_uint4(o1[4], o1[5], o1[6], o1[7]);
}

// pack_w: build the swizzled smem image per chunk (one 16B unit per thread)
__global__ void pack_w_kernel(const float* __restrict__ w) {
    int i = blockIdx.x * 256 + threadIdx.x;     // 4*9*256 = 9216 units
    if (i >= 4 * 9 * 256) return;
    int u     = i & 255;            // unit within tap block = co*2+h
    int tap   = (i >> 8) % 9;
    int chunk = i / (9 * 256);
    int co = u >> 1;
    int h  = u & 1;
    unsigned o[4];
#pragma unroll
    for (int j = 0; j < 4; j++) {
        int ci = chunk * 16 + h * 8 + 2 * j;
        float w0 = w[((size_t)co * 64 + ci) * 9 + tap];
        float w1 = w[((size_t)co * 64 + ci + 1) * 9 + tap];
        __nv_bfloat162 p = __float22bfloat162_rn(make_float2(w0, w1));
        o[j] = *reinterpret_cast<unsigned*>(&p);
    }
    unsigned us = (unsigned)u ^ ((unsigned)(u >> 3) & 1);   // swizzle
    g_wP3[(chunk * 9 + tap) * 256 + us] = make_uint4(o[0], o[1], o[2], o[3]);
}

// ---- smem layout (bytes), double buffered ----
// xs buf: 18x18 sites x 48B = 15552 ; ws buf: 36864
#define SMEM_XS0 0
#define SMEM_XS1 15552
#define SMEM_WS0 31104
#define SMEM_WS1 67968
#define SMEM_BS  104832
#define SMEM_RED 105344
#define SMEM_MBAR 107392
#define SMEM_TOTAL 107520

__device__ __forceinline__ void ldsm4(unsigned r[4], unsigned addr) {
    asm volatile("ldmatrix.sync.aligned.m8n8.x4.shared.b16 {%0,%1,%2,%3}, [%4];"
                 : "=r"(r[0]), "=r"(r[1]), "=r"(r[2]), "=r"(r[3]) : "r"(addr));
}
__device__ __forceinline__ void cp16z(unsigned dst, const void* src, unsigned sz) {
    asm volatile("cp.async.cg.shared.global [%0], [%1], 16, %2;"
                 :: "r"(dst), "l"(src), "r"(sz));
}
__device__ __forceinline__ void mbar_init(unsigned mbar, unsigned cnt) {
    asm volatile("mbarrier.init.shared.b64 [%0], %1;" :: "r"(mbar), "r"(cnt) : "memory");
}
__device__ __forceinline__ void mbar_expect_tx(unsigned mbar, unsigned tx) {
    asm volatile("mbarrier.arrive.expect_tx.shared.b64 _, [%0], %1;"
                 :: "r"(mbar), "r"(tx) : "memory");
}
__device__ __forceinline__ void bulk_g2s(unsigned dst, const void* src,
                                         unsigned sz, unsigned mbar) {
    asm volatile("cp.async.bulk.shared::cta.global.mbarrier::complete_tx::bytes "
                 "[%0], [%1], %2, [%3];"
                 :: "r"(dst), "l"(src), "r"(sz), "r"(mbar) : "memory");
}
__device__ __forceinline__ void mbar_wait(unsigned mbar, unsigned parity) {
    unsigned done;
    asm volatile(
        "{\n\t.reg .pred p;\n\t"
        "mbarrier.try_wait.parity.acquire.cta.shared::cta.b64 p, [%1], %2;\n\t"
        "selp.b32 %0, 1, 0, p;\n\t}"
        : "=r"(done) : "r"(mbar), "r"(parity) : "memory");
    while (!done) {
        asm volatile(
            "{\n\t.reg .pred p;\n\t"
            "mbarrier.try_wait.parity.acquire.cta.shared::cta.b64 p, [%1], %2, 0x989680;\n\t"
            "selp.b32 %0, 1, 0, p;\n\t}"
            : "=r"(done) : "r"(mbar), "r"(parity) : "memory");
    }
}
__device__ __forceinline__ void mma_bf16(float d[4], const unsigned a[4],
                                         unsigned b0, unsigned b1) {
    asm volatile(
        "mma.sync.aligned.m16n8k16.row.col.f32.bf16.bf16.f32 "
        "{%0,%1,%2,%3}, {%4,%5,%6,%7}, {%8,%9}, {%0,%1,%2,%3};\n"
        : "+f"(d[0]), "+f"(d[1]), "+f"(d[2]), "+f"(d[3])
        : "r"(a[0]), "r"(a[1]), "r"(a[2]), "r"(a[3]), "r"(b0), "r"(b1));
}

__global__ __launch_bounds__(512, 1)
void conv_mma_kernel(const float* __restrict__ bias, float* __restrict__ out) {
    extern __shared__ unsigned char sm[];
    const unsigned smb = (unsigned)__cvta_generic_to_shared(sm);

    const int tid  = threadIdx.x;
    const int wid  = tid >> 5;      // 0..15
    const int lane = tid & 31;
    const int q    = lane & 3;
    const int g    = lane >> 2;
    const int pg   = wid >> 1;      // pixel group 0..7: y rows 2pg, 2pg+1
    const int cg   = wid & 1;       // co group
    const int nb   = cg * 64;

    const int x0 = blockIdx.x * TPX;
    const int y0 = blockIdx.y * TPY;
    const int n  = blockIdx.z;

    float* bs  = (float*)(sm + SMEM_BS);
    float* red = (float*)(sm + SMEM_RED);   // [2][16][16]

    if (tid < CO_TOT) bs[tid] = bias[tid];
    if (tid == 0) {
        mbar_init(smb + SMEM_MBAR, 1);
        mbar_init(smb + SMEM_MBAR + 8, 1);
    }
    __syncthreads();

    const unsigned axoff = (unsigned)((lane & 15) * 48 + (lane >> 4) * 16);
    unsigned boff[4];
    {
        int co_off = (lane & 7) | ((lane >> 4) << 3);
        int h      = (lane >> 3) & 1;
#pragma unroll
        for (int t = 0; t < 4; t++) {
            unsigned u = (unsigned)((nb + 16 * t + co_off) * 2 + h);
            u ^= (u >> 3) & 1;
            boff[t] = u * 16;
        }
    }

    float d[2][8][4];
#pragma unroll
    for (int m = 0; m < 2; m++)
#pragma unroll
        for (int t = 0; t < 8; t++)
#pragma unroll
            for (int j = 0; j < 4; j++) d[m][t][j] = 0.0f;

    // ---- prefetch: xs 648 cp.async(16B) + ws ONE bulk copy ----
    auto prefetch = [&](int chunk) {
        int pbuf = chunk & 1;
        unsigned xb = smb + (pbuf ? SMEM_XS1 : SMEM_XS0);
        unsigned wb = smb + (pbuf ? SMEM_WS1 : SMEM_WS0);
        if (tid == 0) {
            unsigned mbar = smb + SMEM_MBAR + pbuf * 8;
            mbar_expect_tx(mbar, 36864u);
            bulk_g2s(wb, &g_wP3[chunk * 9 * 256], 36864u, mbar);
        }
        // xs: 324 sites (18r x 18c), 2 cp16 each
        for (int i = tid; i < 648; i += 512) {
            int site = i >> 1, half = i & 1;
            int r = site / 18, c = site % 18;
            int gy = y0 + r, gx = x0 + c;
            unsigned dst = xb + (unsigned)(site * 48 + half * 16);
            int gyc = gy < 127 ? gy : 127;
            int gxc = gx < 127 ? gx : 127;
            const unsigned* src =
                &g_xP2[((((size_t)n * 4 + chunk) * 128 + gyc) * 128 + gxc) * 8 + half * 4];
            unsigned sz = (gy < HH && gx < WW) ? 16u : 0u;
            cp16z(dst, src, sz);
        }
        asm volatile("cp.async.commit_group;" ::: "memory");
    };

    prefetch(0);

    for (int c = 0; c < 4; c++) {
        asm volatile("cp.async.wait_group 0;" ::: "memory");
        mbar_wait(smb + SMEM_MBAR + (c & 1) * 8, (c >> 1) & 1);
        __syncthreads();
        if (c < 3) prefetch(c + 1);

        unsigned xb = smb + ((c & 1) ? SMEM_XS1 : SMEM_XS0);
        unsigned wb = smb + ((c & 1) ? SMEM_WS1 : SMEM_WS0);
        const unsigned arow = (unsigned)(2 * pg) * 864;   // 2pg rows * 18 sites * 48B

#pragma unroll
        for (int tap = 0; tap < 9; tap++) {
            const int ky = tap / 3, kx = tap % 3;
            unsigned a0[4], a1[4];
            ldsm4(a0, xb + arow + (unsigned)((ky * 18 + kx) * 48) + axoff);
            ldsm4(a1, xb + arow + (unsigned)(((ky + 1) * 18 + kx) * 48) + axoff);
#pragma unroll
            for (int t = 0; t < 4; t++) {
                unsigned b[4];
                ldsm4(b, wb + (unsigned)(tap * 4096) + boff[t]);
                mma_bf16(d[0][2 * t],     a0, b[0], b[1]);
                mma_bf16(d[0][2 * t + 1], a0, b[2], b[3]);
                mma_bf16(d[1][2 * t],     a1, b[0], b[1]);
                mma_bf16(d[1][2 * t + 1], a1, b[2], b[3]);
            }
        }
    }

    // ---- epilogue: +bias, min over this warp's 64 co ----
#pragma unroll
    for (int m = 0; m < 2; m++) {
        float mlo = INFINITY, mhi = INFINITY;
#pragma unroll
        for (int t = 0; t < 8; t++) {
            float b0 = bs[nb + 8 * t + 2 * q];
            float b1 = bs[nb + 8 * t + 2 * q + 1];
            mlo = fminf(mlo, fminf(d[m][t][0] + b0, d[m][t][1] + b1));
            mhi = fminf(mhi, fminf(d[m][t][2] + b0, d[m][t][3] + b1));
        }
        mlo = fminf(mlo, __shfl_xor_sync(0xFFFFFFFFu, mlo, 1));
        mlo = fminf(mlo, __shfl_xor_sync(0xFFFFFFFFu, mlo, 2));
        mhi = fminf(mhi, __shfl_xor_sync(0xFFFFFFFFu, mhi, 1));
        mhi = fminf(mhi, __shfl_xor_sync(0xFFFFFFFFu, mhi, 2));
        if (q == 0) {
            red[(cg * 16 + pg * 2 + m) * 16 + g]     = mlo;
            red[(cg * 16 + pg * 2 + m) * 16 + g + 8] = mhi;
        }
    }
    __syncthreads();

    // ---- combine co-groups, tanh(tanh), store ----
    if (tid < TPY * TPX) {
        int yl = tid >> 4, xl = tid & 15;
        int yy = y0 + yl, xx = x0 + xl;
        if (yy < HO && xx < WO) {
            float v = fminf(red[yl * 16 + xl], red[(16 + yl) * 16 + xl]);
            out[((size_t)n * HO + yy) * WO + xx] = tanhf(tanhf(v));
        }
    }
}

extern "C" void kernel_launch(void* const* d_in, const int* in_sizes, int n_in,
                              void* d_out, int out_size) {
    const float* x    = (const float*)d_in[0];
    const float* w    = (const float*)d_in[1];
    const float* bias = (const float*)d_in[2];
    float* out        = (float*)d_out;

    pack_x_kernel<<<(32u * 4u * 128u * 64u) / 256u, 256>>>(x);
    pack_w_kernel<<<(4 * 9 * 256 + 255) / 256, 256>>>(w);

    cudaFuncSetAttribute(conv_mma_kernel,
                         cudaFuncAttributeMaxDynamicSharedMemorySize, SMEM_TOTAL);

    dim3 grid((WO + TPX - 1) / TPX,   // 8
              (HO + TPY - 1) / TPY,   // 8
              N_IMG);                 // 32
    conv_mma_kernel<<<grid, 512, SMEM_TOTAL>>>(bias, out);
}

// round 11
// speedup vs baseline: 1.1553x; 1.1553x over previous
#include <cuda_runtime.h>
#include <cuda_bf16.h>
#include <math.h>

// Problem constants
#define N_IMG  32
#define CI_TOT 64
#define HH     128
#define WW     128
#define CO_TOT 128
#define HO     126
#define WO     126

#define TPX 16
#define TPY 8

// ---- packed operand scratch (device globals; no allocation) ----
// g_xP2: bf16x2, [n(32)][chunk(4)][h(128)][w(128)][ci2-in-chunk(8)]  (32B per site)
__device__ unsigned g_xP2[32u * 4u * 128u * 128u * 8u];
// g_wP3: pre-swizzled smem byte image of ws: [chunk(4)][tap(9)][256 units x 16B]
__device__ uint4 g_wP3[4 * 9 * 256];

// merged pack kernel: blocks < 8192 pack x (R5-proven path); blocks >= 8192 pack w
__global__ void pack_kernel(const float* __restrict__ x, const float* __restrict__ w) {
    if (blockIdx.x < 8192) {
        unsigned i = blockIdx.x * 256 + threadIdx.x;
        unsigned wq    = i & 127;
        unsigned h     = (i >> 7) & 127;
        unsigned chunk = (i >> 14) & 3;
        unsigned n     = i >> 16;
        const float* src = x + (((size_t)(n * 64 + chunk * 16)) * 128 + h) * 128 + wq;
        unsigned o[8];
#pragma unroll
        for (int c2 = 0; c2 < 8; c2++) {
            float v0 = src[(size_t)(2 * c2) * 16384];
            float v1 = src[(size_t)(2 * c2 + 1) * 16384];
            __nv_bfloat162 p = __float22bfloat162_rn(make_float2(v0, v1));
            o[c2] = *reinterpret_cast<unsigned*>(&p);
        }
        uint4* dst = reinterpret_cast<uint4*>(&g_xP2[(size_t)i * 8]);
        dst[0] = make_uint4(o[0], o[1], o[2], o[3]);
        dst[1] = make_uint4(o[4], o[5], o[6], o[7]);
    } else {
        int i = (blockIdx.x - 8192) * 256 + threadIdx.x;   // 9216 units
        if (i >= 4 * 9 * 256) return;
        int u     = i & 255;            // unit within tap block = co*2+h
        int tap   = (i >> 8) % 9;
        int chunk = i / (9 * 256);
        int co = u >> 1;
        int h  = u & 1;
        unsigned o[4];
#pragma unroll
        for (int j = 0; j < 4; j++) {
            int ci = chunk * 16 + h * 8 + 2 * j;
            float w0 = w[((size_t)co * 64 + ci) * 9 + tap];
            float w1 = w[((size_t)co * 64 + ci + 1) * 9 + tap];
            __nv_bfloat162 p = __float22bfloat162_rn(make_float2(w0, w1));
            o[j] = *reinterpret_cast<unsigned*>(&p);
        }
        unsigned us = (unsigned)u ^ ((unsigned)(u >> 3) & 1);   // swizzle
        g_wP3[(chunk * 9 + tap) * 256 + us] = make_uint4(o[0], o[1], o[2], o[3]);
    }
}

// ---- smem layout (bytes), double buffered ----
#define SMEM_XS0 0
#define SMEM_XS1 8640
#define SMEM_WS0 17280
#define SMEM_WS1 54144
#define SMEM_BS  91008
#define SMEM_RED 91520
#define SMEM_MBAR 92544
#define SMEM_TOTAL 92672

__device__ __forceinline__ void ldsm4(unsigned r[4], unsigned addr) {
    asm volatile("ldmatrix.sync.aligned.m8n8.x4.shared.b16 {%0,%1,%2,%3}, [%4];"
                 : "=r"(r[0]), "=r"(r[1]), "=r"(r[2]), "=r"(r[3]) : "r"(addr));
}
__device__ __forceinline__ void cp16z(unsigned dst, const void* src, unsigned sz) {
    asm volatile("cp.async.cg.shared.global [%0], [%1], 16, %2;"
                 :: "r"(dst), "l"(src), "r"(sz));
}
__device__ __forceinline__ void mbar_init(unsigned mbar, unsigned cnt) {
    asm volatile("mbarrier.init.shared.b64 [%0], %1;" :: "r"(mbar), "r"(cnt) : "memory");
}
__device__ __forceinline__ void mbar_expect_tx(unsigned mbar, unsigned tx) {
    asm volatile("mbarrier.arrive.expect_tx.shared.b64 _, [%0], %1;"
                 :: "r"(mbar), "r"(tx) : "memory");
}
__device__ __forceinline__ void bulk_g2s(unsigned dst, const void* src,
                                         unsigned sz, unsigned mbar) {
    asm volatile("cp.async.bulk.shared::cta.global.mbarrier::complete_tx::bytes "
                 "[%0], [%1], %2, [%3];"
                 :: "r"(dst), "l"(src), "r"(sz), "r"(mbar) : "memory");
}
__device__ __forceinline__ void mbar_wait(unsigned mbar, unsigned parity) {
    unsigned done;
    asm volatile(
        "{\n\t.reg .pred p;\n\t"
        "mbarrier.try_wait.parity.acquire.cta.shared::cta.b64 p, [%1], %2;\n\t"
        "selp.b32 %0, 1, 0, p;\n\t}"
        : "=r"(done) : "r"(mbar), "r"(parity) : "memory");
    while (!done) {
        asm volatile(
            "{\n\t.reg .pred p;\n\t"
            "mbarrier.try_wait.parity.acquire.cta.shared::cta.b64 p, [%1], %2, 0x989680;\n\t"
            "selp.b32 %0, 1, 0, p;\n\t}"
            : "=r"(done) : "r"(mbar), "r"(parity) : "memory");
    }
}
__device__ __forceinline__ void mma_bf16(float d[4], const unsigned a[4],
                                         unsigned b0, unsigned b1) {
    asm volatile(
        "mma.sync.aligned.m16n8k16.row.col.f32.bf16.bf16.f32 "
        "{%0,%1,%2,%3}, {%4,%5,%6,%7}, {%8,%9}, {%0,%1,%2,%3};\n"
        : "+f"(d[0]), "+f"(d[1]), "+f"(d[2]), "+f"(d[3])
        : "r"(a[0]), "r"(a[1]), "r"(a[2]), "r"(a[3]), "r"(b0), "r"(b1));
}

__global__ __launch_bounds__(256, 2)
void conv_mma_kernel(const float* __restrict__ bias, float* __restrict__ out) {
    extern __shared__ unsigned char sm[];
    const unsigned smb = (unsigned)__cvta_generic_to_shared(sm);

    const int tid  = threadIdx.x;
    const int wid  = tid >> 5;
    const int lane = tid & 31;
    const int q    = lane & 3;
    const int g    = lane >> 2;
    const int pg   = wid >> 1;      // pixel group: y rows 2pg, 2pg+1
    const int cg   = wid & 1;       // co group
    const int nb   = cg * 64;

    const int x0 = blockIdx.x * TPX;
    const int y0 = blockIdx.y * TPY;
    const int n  = blockIdx.z;

    float* bs  = (float*)(sm + SMEM_BS);
    float* red = (float*)(sm + SMEM_RED);

    if (tid < CO_TOT) bs[tid] = bias[tid];
    if (tid == 0) {
        mbar_init(smb + SMEM_MBAR, 1);
        mbar_init(smb + SMEM_MBAR + 8, 1);
    }
    __syncthreads();

    const unsigned axoff = (unsigned)((lane & 15) * 48 + (lane >> 4) * 16);
    unsigned boff[4];
    {
        int co_off = (lane & 7) | ((lane >> 4) << 3);
        int h      = (lane >> 3) & 1;
#pragma unroll
        for (int t = 0; t < 4; t++) {
            unsigned u = (unsigned)((nb + 16 * t + co_off) * 2 + h);
            u ^= (u >> 3) & 1;
            boff[t] = u * 16;
        }
    }

    float d[2][8][4];
#pragma unroll
    for (int m = 0; m < 2; m++)
#pragma unroll
        for (int t = 0; t < 8; t++)
#pragma unroll
            for (int j = 0; j < 4; j++) d[m][t][j] = 0.0f;

    // ---- prefetch: xs 360 cp.async(16B) + ws ONE bulk copy ----
    auto prefetch = [&](int chunk) {
        int pbuf = chunk & 1;
        unsigned xb = smb + (pbuf ? SMEM_XS1 : SMEM_XS0);
        unsigned wb = smb + (pbuf ? SMEM_WS1 : SMEM_WS0);
        if (tid == 0) {
            unsigned mbar = smb + SMEM_MBAR + pbuf * 8;
            mbar_expect_tx(mbar, 36864u);
            bulk_g2s(wb, &g_wP3[chunk * 9 * 256], 36864u, mbar);
        }
        for (int i = tid; i < 360; i += 256) {
            int site = i >> 1, half = i & 1;
            int r = site / 18, c = site % 18;
            int gy = y0 + r, gx = x0 + c;
            unsigned dst = xb + (unsigned)(site * 48 + half * 16);
            int gyc = gy < 127 ? gy : 127;
            int gxc = gx < 127 ? gx : 127;
            const unsigned* src =
                &g_xP2[((((size_t)n * 4 + chunk) * 128 + gyc) * 128 + gxc) * 8 + half * 4];
            unsigned sz = (gy < HH && gx < WW) ? 16u : 0u;
            cp16z(dst, src, sz);
        }
        asm volatile("cp.async.commit_group;" ::: "memory");
    };

    prefetch(0);

    for (int c = 0; c < 4; c++) {
        asm volatile("cp.async.wait_group 0;" ::: "memory");
        mbar_wait(smb + SMEM_MBAR + (c & 1) * 8, (c >> 1) & 1);
        __syncthreads();
        if (c < 3) prefetch(c + 1);

        unsigned xb = smb + ((c & 1) ? SMEM_XS1 : SMEM_XS0);
        unsigned wb = smb + ((c & 1) ? SMEM_WS1 : SMEM_WS0);
        const unsigned arow = (unsigned)(2 * pg) * 864;

        // kx-outer: load 4 A row-fragments once, reuse across ky (a1 of ky == a0 of ky+1)
#pragma unroll
        for (int kx = 0; kx < 3; kx++) {
            unsigned a[4][4];
#pragma unroll
            for (int rr = 0; rr < 4; rr++)
                ldsm4(a[rr], xb + arow + (unsigned)(((rr)*18 + kx) * 48) + axoff);
#pragma unroll
            for (int ky = 0; ky < 3; ky++) {
                const int tap = ky * 3 + kx;
#pragma unroll
                for (int t = 0; t < 4; t++) {
                    unsigned b[4];
                    ldsm4(b, wb + (unsigned)(tap * 4096) + boff[t]);
                    mma_bf16(d[0][2 * t],     a[ky],     b[0], b[1]);
                    mma_bf16(d[0][2 * t + 1], a[ky],     b[2], b[3]);
                    mma_bf16(d[1][2 * t],     a[ky + 1], b[0], b[1]);
                    mma_bf16(d[1][2 * t + 1], a[ky + 1], b[2], b[3]);
                }
            }
        }
    }

    // ---- epilogue: +bias, min over this warp's 64 co ----
#pragma unroll
    for (int m = 0; m < 2; m++) {
        float mlo = INFINITY, mhi = INFINITY;
#pragma unroll
        for (int t = 0; t < 8; t++) {
            float b0 = bs[nb + 8 * t + 2 * q];
            float b1 = bs[nb + 8 * t + 2 * q + 1];
            mlo = fminf(mlo, fminf(d[m][t][0] + b0, d[m][t][1] + b1));
            mhi = fminf(mhi, fminf(d[m][t][2] + b0, d[m][t][3] + b1));
        }
        mlo = fminf(mlo, __shfl_xor_sync(0xFFFFFFFFu, mlo, 1));
        mlo = fminf(mlo, __shfl_xor_sync(0xFFFFFFFFu, mlo, 2));
        mhi = fminf(mhi, __shfl_xor_sync(0xFFFFFFFFu, mhi, 1));
        mhi = fminf(mhi, __shfl_xor_sync(0xFFFFFFFFu, mhi, 2));
        if (q == 0) {
            red[(cg * 8 + pg * 2 + m) * 16 + g]     = mlo;
            red[(cg * 8 + pg * 2 + m) * 16 + g + 8] = mhi;
        }
    }
    __syncthreads();

    if (tid < TPY * TPX) {
        int yl = tid >> 4, xl = tid & 15;
        int yy = y0 + yl, xx = x0 + xl;
        if (yy < HO && xx < WO) {
            float v = fminf(red[yl * 16 + xl], red[(8 + yl) * 16 + xl]);
            out[((size_t)n * HO + yy) * WO + xx] = tanhf(tanhf(v));
        }
    }
}

extern "C" void kernel_launch(void* const* d_in, const int* in_sizes, int n_in,
                              void* d_out, int out_size) {
    const float* x    = (const float*)d_in[0];
    const float* w    = (const float*)d_in[1];
    const float* bias = (const float*)d_in[2];
    float* out        = (float*)d_out;

    pack_kernel<<<8192 + 36, 256>>>(x, w);

    cudaFuncSetAttribute(conv_mma_kernel,
                         cudaFuncAttributeMaxDynamicSharedMemorySize, SMEM_TOTAL);

    dim3 grid((WO + TPX - 1) / TPX,   // 8
              (HO + TPY - 1) / TPY,   // 16
              N_IMG);                 // 32
    conv_mma_kernel<<<grid, 256, SMEM_TOTAL>>>(bias, out);
}

// round 12
// speedup vs baseline: 1.1874x; 1.0277x over previous
#include <cuda_runtime.h>
#include <cuda_bf16.h>
#include <math.h>

// Problem constants
#define N_IMG  32
#define CI_TOT 64
#define HH     128
#define WW     128
#define CO_TOT 128
#define HO     126
#define WO     126

#define TPX 16
#define TPY 8

// ---- packed operand scratch (device globals; no allocation) ----
// g_xP2: bf16x2, [n(32)][chunk(4)][h(128)] rows of 256 swizzled 16B units
//        unit u (= w*2 + half) stored at u ^ ((u>>3)&1).  +1024 tail pad.
__device__ unsigned g_xP2[32u * 4u * 128u * 128u * 8u + 1024u];
// g_wP3: pre-swizzled smem byte image of ws: [chunk(4)][tap(9)][256 units x 16B]
__device__ uint4 g_wP3[4 * 9 * 256];

// merged pack kernel: blocks < 8192 pack x; blocks >= 8192 pack w
__global__ void pack_kernel(const float* __restrict__ x, const float* __restrict__ w) {
    if (blockIdx.x < 8192) {
        unsigned i = blockIdx.x * 256 + threadIdx.x;
        unsigned wq    = i & 127;
        unsigned h     = (i >> 7) & 127;
        unsigned chunk = (i >> 14) & 3;
        unsigned n     = i >> 16;
        const float* src = x + (((size_t)(n * 64 + chunk * 16)) * 128 + h) * 128 + wq;
        unsigned o[8];
#pragma unroll
        for (int c2 = 0; c2 < 8; c2++) {
            float v0 = src[(size_t)(2 * c2) * 16384];
            float v1 = src[(size_t)(2 * c2 + 1) * 16384];
            __nv_bfloat162 p = __float22bfloat162_rn(make_float2(v0, v1));
            o[c2] = *reinterpret_cast<unsigned*>(&p);
        }
        // row base (in unsigneds): 1024 per row
        size_t rowb = (size_t)(((n * 4 + chunk) * 128 + h)) * 1024;
        unsigned u0 = wq * 2, u1 = wq * 2 + 1;
        unsigned s0 = u0 ^ ((u0 >> 3) & 1);
        unsigned s1 = u1 ^ ((u1 >> 3) & 1);
        *reinterpret_cast<uint4*>(&g_xP2[rowb + s0 * 4]) =
            make_uint4(o[0], o[1], o[2], o[3]);
        *reinterpret_cast<uint4*>(&g_xP2[rowb + s1 * 4]) =
            make_uint4(o[4], o[5], o[6], o[7]);
    } else {
        int i = (blockIdx.x - 8192) * 256 + threadIdx.x;   // 9216 units
        if (i >= 4 * 9 * 256) return;
        int u     = i & 255;
        int tap   = (i >> 8) % 9;
        int chunk = i / (9 * 256);
        int co = u >> 1;
        int h  = u & 1;
        unsigned o[4];
#pragma unroll
        for (int j = 0; j < 4; j++) {
            int ci = chunk * 16 + h * 8 + 2 * j;
            float w0 = w[((size_t)co * 64 + ci) * 9 + tap];
            float w1 = w[((size_t)co * 64 + ci + 1) * 9 + tap];
            __nv_bfloat162 p = __float22bfloat162_rn(make_float2(w0, w1));
            o[j] = *reinterpret_cast<unsigned*>(&p);
        }
        unsigned us = (unsigned)u ^ ((unsigned)(u >> 3) & 1);
        g_wP3[(chunk * 9 + tap) * 256 + us] = make_uint4(o[0], o[1], o[2], o[3]);
    }
}

// ---- smem layout (bytes), double buffered ----
// xs buf: 10 rows x 640B (576 data + 64 pad; 128B-aligned rows) = 6400
// ws buf: 36864
#define SMEM_XS0 0
#define SMEM_XS1 6400
#define SMEM_WS0 12800
#define SMEM_WS1 49664
#define SMEM_BS  86528
#define SMEM_RED 87040
#define SMEM_MBAR 88064
#define SMEM_TOTAL 88192

#define XS_ROW_STRIDE 640

__device__ __forceinline__ void ldsm4(unsigned r[4], unsigned addr) {
    asm volatile("ldmatrix.sync.aligned.m8n8.x4.shared.b16 {%0,%1,%2,%3}, [%4];"
                 : "=r"(r[0]), "=r"(r[1]), "=r"(r[2]), "=r"(r[3]) : "r"(addr));
}
__device__ __forceinline__ void mbar_init(unsigned mbar, unsigned cnt) {
    asm volatile("mbarrier.init.shared.b64 [%0], %1;" :: "r"(mbar), "r"(cnt) : "memory");
}
__device__ __forceinline__ void mbar_expect_tx(unsigned mbar, unsigned tx) {
    asm volatile("mbarrier.arrive.expect_tx.shared.b64 _, [%0], %1;"
                 :: "r"(mbar), "r"(tx) : "memory");
}
__device__ __forceinline__ void bulk_g2s(unsigned dst, const void* src,
                                         unsigned sz, unsigned mbar) {
    asm volatile("cp.async.bulk.shared::cta.global.mbarrier::complete_tx::bytes "
                 "[%0], [%1], %2, [%3];"
                 :: "r"(dst), "l"(src), "r"(sz), "r"(mbar) : "memory");
}
__device__ __forceinline__ void mbar_wait(unsigned mbar, unsigned parity) {
    unsigned done;
    asm volatile(
        "{\n\t.reg .pred p;\n\t"
        "mbarrier.try_wait.parity.acquire.cta.shared::cta.b64 p, [%1], %2;\n\t"
        "selp.b32 %0, 1, 0, p;\n\t}"
        : "=r"(done) : "r"(mbar), "r"(parity) : "memory");
    while (!done) {
        asm volatile(
            "{\n\t.reg .pred p;\n\t"
            "mbarrier.try_wait.parity.acquire.cta.shared::cta.b64 p, [%1], %2, 0x989680;\n\t"
            "selp.b32 %0, 1, 0, p;\n\t}"
            : "=r"(done) : "r"(mbar), "r"(parity) : "memory");
    }
}
__device__ __forceinline__ void mma_bf16(float d[4], const unsigned a[4],
                                         unsigned b0, unsigned b1) {
    asm volatile(
        "mma.sync.aligned.m16n8k16.row.col.f32.bf16.bf16.f32 "
        "{%0,%1,%2,%3}, {%4,%5,%6,%7}, {%8,%9}, {%0,%1,%2,%3};\n"
        : "+f"(d[0]), "+f"(d[1]), "+f"(d[2]), "+f"(d[3])
        : "r"(a[0]), "r"(a[1]), "r"(a[2]), "r"(a[3]), "r"(b0), "r"(b1));
}

__global__ __launch_bounds__(256, 2)
void conv_mma_kernel(const float* __restrict__ bias, float* __restrict__ out) {
    extern __shared__ unsigned char sm[];
    const unsigned smb = (unsigned)__cvta_generic_to_shared(sm);

    const int tid  = threadIdx.x;
    const int wid  = tid >> 5;
    const int lane = tid & 31;
    const int q    = lane & 3;
    const int g    = lane >> 2;
    const int pg   = wid >> 1;      // pixel group: y rows 2pg, 2pg+1
    const int cg   = wid & 1;       // co group
    const int nb   = cg * 64;

    const int x0 = blockIdx.x * TPX;
    const int y0 = blockIdx.y * TPY;
    const int n  = blockIdx.z;

    float* bs  = (float*)(sm + SMEM_BS);
    float* red = (float*)(sm + SMEM_RED);

    if (tid < CO_TOT) bs[tid] = bias[tid];
    if (tid == 0) {
        mbar_init(smb + SMEM_MBAR, 1);
        mbar_init(smb + SMEM_MBAR + 8, 1);
    }
    __syncthreads();

    // per-lane swizzled A offsets, one per kx shift
    unsigned axk[3];
#pragma unroll
    for (int kx = 0; kx < 3; kx++) {
        unsigned u = (unsigned)((kx + (lane & 15)) * 2 + (lane >> 4));
        axk[kx] = (u ^ ((u >> 3) & 1)) * 16;
    }
    unsigned boff[4];
    {
        int co_off = (lane & 7) | ((lane >> 4) << 3);
        int h      = (lane >> 3) & 1;
#pragma unroll
        for (int t = 0; t < 4; t++) {
            unsigned u = (unsigned)((nb + 16 * t + co_off) * 2 + h);
            u ^= (u >> 3) & 1;
            boff[t] = u * 16;
        }
    }

    float d[2][8][4];
#pragma unroll
    for (int m = 0; m < 2; m++)
#pragma unroll
        for (int t = 0; t < 8; t++)
#pragma unroll
            for (int j = 0; j < 4; j++) d[m][t][j] = 0.0f;

    // ---- prefetch: ALL staging via bulk copies (1 ws + 10 xs rows) ----
    auto prefetch = [&](int chunk) {
        if (tid != 0) return;
        int pbuf = chunk & 1;
        unsigned xb = smb + (pbuf ? SMEM_XS1 : SMEM_XS0);
        unsigned wb = smb + (pbuf ? SMEM_WS1 : SMEM_WS0);
        unsigned mbar = smb + SMEM_MBAR + pbuf * 8;
        mbar_expect_tx(mbar, 36864u + 10u * 576u);
        bulk_g2s(wb, &g_wP3[chunk * 9 * 256], 36864u, mbar);
#pragma unroll
        for (int r = 0; r < 10; r++) {
            int gy = y0 + r;
            int gyc = gy < 127 ? gy : 127;
            const unsigned* src =
                &g_xP2[((size_t)((n * 4 + chunk) * 128 + gyc)) * 1024 + (size_t)x0 * 8];
            bulk_g2s(xb + (unsigned)(r * XS_ROW_STRIDE), src, 576u, mbar);
        }
    };

    prefetch(0);

    for (int c = 0; c < 4; c++) {
        mbar_wait(smb + SMEM_MBAR + (c & 1) * 8, (c >> 1) & 1);
        __syncthreads();
        if (c < 3) prefetch(c + 1);

        unsigned xb = smb + ((c & 1) ? SMEM_XS1 : SMEM_XS0);
        unsigned wb = smb + ((c & 1) ? SMEM_WS1 : SMEM_WS0);
        const unsigned arow = (unsigned)(2 * pg) * XS_ROW_STRIDE;

        // kx-outer: load 4 A row-fragments once, reuse across ky
#pragma unroll
        for (int kx = 0; kx < 3; kx++) {
            unsigned a[4][4];
#pragma unroll
            for (int rr = 0; rr < 4; rr++)
                ldsm4(a[rr], xb + arow + (unsigned)(rr * XS_ROW_STRIDE) + axk[kx]);
#pragma unroll
            for (int ky = 0; ky < 3; ky++) {
                const int tap = ky * 3 + kx;
#pragma unroll
                for (int t = 0; t < 4; t++) {
                    unsigned b[4];
                    ldsm4(b, wb + (unsigned)(tap * 4096) + boff[t]);
                    mma_bf16(d[0][2 * t],     a[ky],     b[0], b[1]);
                    mma_bf16(d[0][2 * t + 1], a[ky],     b[2], b[3]);
                    mma_bf16(d[1][2 * t],     a[ky + 1], b[0], b[1]);
                    mma_bf16(d[1][2 * t + 1], a[ky + 1], b[2], b[3]);
                }
            }
        }
    }

    // ---- epilogue: +bias, min over this warp's 64 co ----
#pragma unroll
    for (int m = 0; m < 2; m++) {
        float mlo = INFINITY, mhi = INFINITY;
#pragma unroll
        for (int t = 0; t < 8; t++) {
            float b0 = bs[nb + 8 * t + 2 * q];
            float b1 = bs[nb + 8 * t + 2 * q + 1];
            mlo = fminf(mlo, fminf(d[m][t][0] + b0, d[m][t][1] + b1));
            mhi = fminf(mhi, fminf(d[m][t][2] + b0, d[m][t][3] + b1));
        }
        mlo = fminf(mlo, __shfl_xor_sync(0xFFFFFFFFu, mlo, 1));
        mlo = fminf(mlo, __shfl_xor_sync(0xFFFFFFFFu, mlo, 2));
        mhi = fminf(mhi, __shfl_xor_sync(0xFFFFFFFFu, mhi, 1));
        mhi = fminf(mhi, __shfl_xor_sync(0xFFFFFFFFu, mhi, 2));
        if (q == 0) {
            red[(cg * 8 + pg * 2 + m) * 16 + g]     = mlo;
            red[(cg * 8 + pg * 2 + m) * 16 + g + 8] = mhi;
        }
    }
    __syncthreads();

    if (tid < TPY * TPX) {
        int yl = tid >> 4, xl = tid & 15;
        int yy = y0 + yl, xx = x0 + xl;
        if (yy < HO && xx < WO) {
            float v = fminf(red[yl * 16 + xl], red[(8 + yl) * 16 + xl]);
            out[((size_t)n * HO + yy) * WO + xx] = tanhf(tanhf(v));
        }
    }
}

extern "C" void kernel_launch(void* const* d_in, const int* in_sizes, int n_in,
                              void* d_out, int out_size) {
    const float* x    = (const float*)d_in[0];
    const float* w    = (const float*)d_in[1];
    const float* bias = (const float*)d_in[2];
    float* out        = (float*)d_out;

    pack_kernel<<<8192 + 36, 256>>>(x, w);

    cudaFuncSetAttribute(conv_mma_kernel,
                         cudaFuncAttributeMaxDynamicSharedMemorySize, SMEM_TOTAL);

    dim3 grid((WO + TPX - 1) / TPX,   // 8
              (HO + TPY - 1) / TPY,   // 16
              N_IMG);                 // 32
    conv_mma_kernel<<<grid, 256, SMEM_TOTAL>>>(bias, out);
}

// round 13
// speedup vs baseline: 1.2049x; 1.0148x over previous
#include <cuda_runtime.h>
#include <cuda_bf16.h>
#include <math.h>

// Problem constants
#define N_IMG  32
#define CI_TOT 64
#define HH     128
#define WW     128
#define CO_TOT 128
#define HO     126
#define WO     126

#define TPX 16
#define TPY 8

// ---- packed operand scratch (device globals; no allocation) ----
// g_xP2: bf16x2, [n(32)][chunk(4)][h(128)] rows of 256 swizzled 16B units
//        unit u (= w*2 + half) stored at u ^ ((u>>3)&1).  +1024 tail pad.
__device__ unsigned g_xP2[32u * 4u * 128u * 128u * 8u + 1024u];
// g_wP3: pre-swizzled smem byte image of ws: [chunk(4)][tap(9)][256 units x 16B]
__device__ uint4 g_wP3[4 * 9 * 256];

// merged pack kernel: blocks < 8192 pack x; blocks >= 8192 pack w
__global__ void pack_kernel(const float* __restrict__ x, const float* __restrict__ w) {
    if (blockIdx.x < 8192) {
        unsigned i = blockIdx.x * 256 + threadIdx.x;
        unsigned wq    = i & 127;
        unsigned h     = (i >> 7) & 127;
        unsigned chunk = (i >> 14) & 3;
        unsigned n     = i >> 16;
        const float* src = x + (((size_t)(n * 64 + chunk * 16)) * 128 + h) * 128 + wq;
        unsigned o[8];
#pragma unroll
        for (int c2 = 0; c2 < 8; c2++) {
            float v0 = src[(size_t)(2 * c2) * 16384];
            float v1 = src[(size_t)(2 * c2 + 1) * 16384];
            __nv_bfloat162 p = __float22bfloat162_rn(make_float2(v0, v1));
            o[c2] = *reinterpret_cast<unsigned*>(&p);
        }
        size_t rowb = (size_t)(((n * 4 + chunk) * 128 + h)) * 1024;
        unsigned u0 = wq * 2, u1 = wq * 2 + 1;
        unsigned s0 = u0 ^ ((u0 >> 3) & 1);
        unsigned s1 = u1 ^ ((u1 >> 3) & 1);
        *reinterpret_cast<uint4*>(&g_xP2[rowb + s0 * 4]) =
            make_uint4(o[0], o[1], o[2], o[3]);
        *reinterpret_cast<uint4*>(&g_xP2[rowb + s1 * 4]) =
            make_uint4(o[4], o[5], o[6], o[7]);
    } else {
        int i = (blockIdx.x - 8192) * 256 + threadIdx.x;   // 9216 units
        if (i >= 4 * 9 * 256) return;
        int u     = i & 255;
        int tap   = (i >> 8) % 9;
        int chunk = i / (9 * 256);
        int co = u >> 1;
        int h  = u & 1;
        unsigned o[4];
#pragma unroll
        for (int j = 0; j < 4; j++) {
            int ci = chunk * 16 + h * 8 + 2 * j;
            float w0 = w[((size_t)co * 64 + ci) * 9 + tap];
            float w1 = w[((size_t)co * 64 + ci + 1) * 9 + tap];
            __nv_bfloat162 p = __float22bfloat162_rn(make_float2(w0, w1));
            o[j] = *reinterpret_cast<unsigned*>(&p);
        }
        unsigned us = (unsigned)u ^ ((unsigned)(u >> 3) & 1);
        g_wP3[(chunk * 9 + tap) * 256 + us] = make_uint4(o[0], o[1], o[2], o[3]);
    }
}

// ---- smem layout (bytes), double buffered ----
#define SMEM_XS0 0
#define SMEM_XS1 6400
#define SMEM_WS0 12800
#define SMEM_WS1 49664
#define SMEM_BS  86528
#define SMEM_RED 87040
#define SMEM_MBAR 89088
#define SMEM_TOTAL 89216

#define XS_ROW_STRIDE 640

__device__ __forceinline__ void ldsm4(unsigned r[4], unsigned addr) {
    asm volatile("ldmatrix.sync.aligned.m8n8.x4.shared.b16 {%0,%1,%2,%3}, [%4];"
                 : "=r"(r[0]), "=r"(r[1]), "=r"(r[2]), "=r"(r[3]) : "r"(addr));
}
__device__ __forceinline__ void mbar_init(unsigned mbar, unsigned cnt) {
    asm volatile("mbarrier.init.shared.b64 [%0], %1;" :: "r"(mbar), "r"(cnt) : "memory");
}
__device__ __forceinline__ void mbar_expect_tx(unsigned mbar, unsigned tx) {
    asm volatile("mbarrier.arrive.expect_tx.shared.b64 _, [%0], %1;"
                 :: "r"(mbar), "r"(tx) : "memory");
}
__device__ __forceinline__ void bulk_g2s(unsigned dst, const void* src,
                                         unsigned sz, unsigned mbar) {
    asm volatile("cp.async.bulk.shared::cta.global.mbarrier::complete_tx::bytes "
                 "[%0], [%1], %2, [%3];"
                 :: "r"(dst), "l"(src), "r"(sz), "r"(mbar) : "memory");
}
__device__ __forceinline__ void mbar_wait(unsigned mbar, unsigned parity) {
    unsigned done;
    asm volatile(
        "{\n\t.reg .pred p;\n\t"
        "mbarrier.try_wait.parity.acquire.cta.shared::cta.b64 p, [%1], %2;\n\t"
        "selp.b32 %0, 1, 0, p;\n\t}"
        : "=r"(done) : "r"(mbar), "r"(parity) : "memory");
    while (!done) {
        asm volatile(
            "{\n\t.reg .pred p;\n\t"
            "mbarrier.try_wait.parity.acquire.cta.shared::cta.b64 p, [%1], %2, 0x989680;\n\t"
            "selp.b32 %0, 1, 0, p;\n\t}"
            : "=r"(done) : "r"(mbar), "r"(parity) : "memory");
    }
}
__device__ __forceinline__ void mma_bf16(float d[4], const unsigned a[4],
                                         unsigned b0, unsigned b1) {
    asm volatile(
        "mma.sync.aligned.m16n8k16.row.col.f32.bf16.bf16.f32 "
        "{%0,%1,%2,%3}, {%4,%5,%6,%7}, {%8,%9}, {%0,%1,%2,%3};\n"
        : "+f"(d[0]), "+f"(d[1]), "+f"(d[2]), "+f"(d[3])
        : "r"(a[0]), "r"(a[1]), "r"(a[2]), "r"(a[3]), "r"(b0), "r"(b1));
}

__global__ __launch_bounds__(256, 2)
void conv_mma_kernel(const float* __restrict__ bias, float* __restrict__ out) {
    extern __shared__ unsigned char sm[];
    const unsigned smb = (unsigned)__cvta_generic_to_shared(sm);

    const int tid  = threadIdx.x;
    const int wid  = tid >> 5;
    const int lane = tid & 31;
    const int q    = lane & 3;
    const int g    = lane >> 2;
    const int pg   = wid >> 2;      // pixel group: y rows 4pg..4pg+3
    const int cg   = wid & 3;       // co group: cg*32..+31
    const int nb   = cg * 32;

    const int x0 = blockIdx.x * TPX;
    const int y0 = blockIdx.y * TPY;
    const int n  = blockIdx.z;

    float* bs  = (float*)(sm + SMEM_BS);
    float* red = (float*)(sm + SMEM_RED);   // [4 cg][8 rows][16 x]

    if (tid < CO_TOT) bs[tid] = bias[tid];
    if (tid == 0) {
        mbar_init(smb + SMEM_MBAR, 1);
        mbar_init(smb + SMEM_MBAR + 8, 1);
    }
    __syncthreads();

    // per-lane swizzled A offsets, one per kx shift
    unsigned axk[3];
#pragma unroll
    for (int kx = 0; kx < 3; kx++) {
        unsigned u = (unsigned)((kx + (lane & 15)) * 2 + (lane >> 4));
        axk[kx] = (u ^ ((u >> 3) & 1)) * 16;
    }
    // B offsets: 2 ldsm4 cover this warp's 32 co
    unsigned boff[2];
    {
        int co_off = (lane & 7) | ((lane >> 4) << 3);
        int h      = (lane >> 3) & 1;
#pragma unroll
        for (int t = 0; t < 2; t++) {
            unsigned u = (unsigned)((nb + 16 * t + co_off) * 2 + h);
            u ^= (u >> 3) & 1;
            boff[t] = u * 16;
        }
    }

    float d[4][4][4];   // [m-tile (y row)][n-tile][frag]
#pragma unroll
    for (int m = 0; m < 4; m++)
#pragma unroll
        for (int t = 0; t < 4; t++)
#pragma unroll
            for (int j = 0; j < 4; j++) d[m][t][j] = 0.0f;

    // ---- prefetch: ALL staging via bulk copies (1 ws + 10 xs rows) ----
    auto prefetch = [&](int chunk) {
        if (tid != 0) return;
        int pbuf = chunk & 1;
        unsigned xb = smb + (pbuf ? SMEM_XS1 : SMEM_XS0);
        unsigned wb = smb + (pbuf ? SMEM_WS1 : SMEM_WS0);
        unsigned mbar = smb + SMEM_MBAR + pbuf * 8;
        mbar_expect_tx(mbar, 36864u + 10u * 576u);
        bulk_g2s(wb, &g_wP3[chunk * 9 * 256], 36864u, mbar);
#pragma unroll
        for (int r = 0; r < 10; r++) {
            int gy = y0 + r;
            int gyc = gy < 127 ? gy : 127;
            const unsigned* src =
                &g_xP2[((size_t)((n * 4 + chunk) * 128 + gyc)) * 1024 + (size_t)x0 * 8];
            bulk_g2s(xb + (unsigned)(r * XS_ROW_STRIDE), src, 576u, mbar);
        }
    };

    prefetch(0);

    for (int c = 0; c < 4; c++) {
        mbar_wait(smb + SMEM_MBAR + (c & 1) * 8, (c >> 1) & 1);
        __syncthreads();
        if (c < 3) prefetch(c + 1);

        unsigned xb = smb + ((c & 1) ? SMEM_XS1 : SMEM_XS0);
        unsigned wb = smb + ((c & 1) ? SMEM_WS1 : SMEM_WS0);
        const unsigned arow = (unsigned)(4 * pg) * XS_ROW_STRIDE;

        // kx-outer: 6 A row-fragments loaded once, reused across ky AND 4 m-tiles
#pragma unroll
        for (int kx = 0; kx < 3; kx++) {
            unsigned a[6][4];
#pragma unroll
            for (int rr = 0; rr < 6; rr++)
                ldsm4(a[rr], xb + arow + (unsigned)(rr * XS_ROW_STRIDE) + axk[kx]);
#pragma unroll
            for (int ky = 0; ky < 3; ky++) {
                const int tap = ky * 3 + kx;
#pragma unroll
                for (int t = 0; t < 2; t++) {
                    unsigned b[4];
                    ldsm4(b, wb + (unsigned)(tap * 4096) + boff[t]);
#pragma unroll
                    for (int m = 0; m < 4; m++) {
                        mma_bf16(d[m][2 * t],     a[m + ky], b[0], b[1]);
                        mma_bf16(d[m][2 * t + 1], a[m + ky], b[2], b[3]);
                    }
                }
            }
        }
    }

    // ---- epilogue: +bias, min over this warp's 32 co ----
#pragma unroll
    for (int m = 0; m < 4; m++) {
        float mlo = INFINITY, mhi = INFINITY;
#pragma unroll
        for (int t = 0; t < 4; t++) {
            float b0 = bs[nb + 8 * t + 2 * q];
            float b1 = bs[nb + 8 * t + 2 * q + 1];
            mlo = fminf(mlo, fminf(d[m][t][0] + b0, d[m][t][1] + b1));
            mhi = fminf(mhi, fminf(d[m][t][2] + b0, d[m][t][3] + b1));
        }
        mlo = fminf(mlo, __shfl_xor_sync(0xFFFFFFFFu, mlo, 1));
        mlo = fminf(mlo, __shfl_xor_sync(0xFFFFFFFFu, mlo, 2));
        mhi = fminf(mhi, __shfl_xor_sync(0xFFFFFFFFu, mhi, 1));
        mhi = fminf(mhi, __shfl_xor_sync(0xFFFFFFFFu, mhi, 2));
        if (q == 0) {
            red[(cg * 8 + pg * 4 + m) * 16 + g]     = mlo;
            red[(cg * 8 + pg * 4 + m) * 16 + g + 8] = mhi;
        }
    }
    __syncthreads();

    // ---- combine 4 co-groups, tanh(tanh), store ----
    if (tid < TPY * TPX) {
        int yl = tid >> 4, xl = tid & 15;
        int yy = y0 + yl, xx = x0 + xl;
        if (yy < HO && xx < WO) {
            float v = fminf(fminf(red[yl * 16 + xl], red[(8 + yl) * 16 + xl]),
                            fminf(red[(16 + yl) * 16 + xl], red[(24 + yl) * 16 + xl]));
            out[((size_t)n * HO + yy) * WO + xx] = tanhf(tanhf(v));
        }
    }
}

extern "C" void kernel_launch(void* const* d_in, const int* in_sizes, int n_in,
                              void* d_out, int out_size) {
    const float* x    = (const float*)d_in[0];
    const float* w    = (const float*)d_in[1];
    const float* bias = (const float*)d_in[2];
    float* out        = (float*)d_out;

    pack_kernel<<<8192 + 36, 256>>>(x, w);

    cudaFuncSetAttribute(conv_mma_kernel,
                         cudaFuncAttributeMaxDynamicSharedMemorySize, SMEM_TOTAL);

    dim3 grid((WO + TPX - 1) / TPX,   // 8
              (HO + TPY - 1) / TPY,   // 16
              N_IMG);                 // 32
    conv_mma_kernel<<<grid, 256, SMEM_TOTAL>>>(bias, out);
}